// round 1
// baseline (speedup 1.0000x reference)
#include <cuda_runtime.h>
#include <math.h>

// Problem constants
#define BB 4
#define CC 128
#define NN 16384
#define MM 4096
#define KK 16

// Scratch (allocation-free rule: __device__ globals)
__device__ float g_featT[BB * NN * CC];    // (B,N,C)  33.5 MB
__device__ float g_pooled[BB * MM * CC];   // (B,M,C)   8 MB
__device__ int   g_knn[BB * NN * 3];
__device__ float g_wgt[BB * NN * 3];

// ---------------- packed f32x2 helpers (sm_103a) ----------------
__device__ __forceinline__ unsigned long long pk2(float lo, float hi) {
    unsigned long long r;
    asm("mov.b64 %0, {%1, %2};" : "=l"(r) : "f"(lo), "f"(hi));
    return r;
}
__device__ __forceinline__ void upk2(float& lo, float& hi, unsigned long long v) {
    asm("mov.b64 {%0, %1}, %2;" : "=f"(lo), "=f"(hi) : "l"(v));
}
__device__ __forceinline__ unsigned long long fma2(unsigned long long a, unsigned long long b, unsigned long long c) {
    unsigned long long r;
    asm("fma.rn.f32x2 %0, %1, %2, %3;" : "=l"(r) : "l"(a), "l"(b), "l"(c));
    return r;
}
__device__ __forceinline__ unsigned long long mul2(unsigned long long a, unsigned long long b) {
    unsigned long long r;
    asm("mul.rn.f32x2 %0, %1, %2;" : "=l"(r) : "l"(a), "l"(b));
    return r;
}
__device__ __forceinline__ unsigned long long add2(unsigned long long a, unsigned long long b) {
    unsigned long long r;
    asm("add.rn.f32x2 %0, %1, %2;" : "=l"(r) : "l"(a), "l"(b));
    return r;
}

// ---------------- Kernel A: transpose feature (B,C,N) -> (B,N,C) ----------------
__global__ void transpose_kernel(const float* __restrict__ feat) {
    __shared__ float tile[32][33];
    int b  = blockIdx.z;
    int n0 = blockIdx.x * 32;
    int c0 = blockIdx.y * 32;
    int tx = threadIdx.x, ty = threadIdx.y;   // 32 x 8
    const float* fb = feat + (size_t)b * CC * NN;
    #pragma unroll
    for (int i = 0; i < 32; i += 8)
        tile[ty + i][tx] = fb[(size_t)(c0 + ty + i) * NN + n0 + tx];
    __syncthreads();
    float* ft = g_featT + (size_t)b * NN * CC;
    #pragma unroll
    for (int i = 0; i < 32; i += 8)
        ft[(size_t)(n0 + ty + i) * CC + c0 + tx] = tile[tx][ty + i];
}

// ---------------- Kernel B: pooled[b,m,c] = max_k featT[b, idx[b,m,k], c] ----------------
__global__ void pool_kernel(const int* __restrict__ pool_idx) {
    int b = blockIdx.y;
    int m = blockIdx.x;
    int c = threadIdx.x;  // 128
    __shared__ int sidx[KK];
    if (threadIdx.x < KK)
        sidx[threadIdx.x] = pool_idx[((size_t)b * MM + m) * KK + threadIdx.x];
    __syncthreads();
    const float* fb = g_featT + (size_t)b * NN * CC;
    float v = -INFINITY;
    #pragma unroll
    for (int k = 0; k < KK; k++)
        v = fmaxf(v, fb[(size_t)sidx[k] * CC + c]);
    g_pooled[((size_t)b * MM + m) * CC + c] = v;
}

// ---------------- Kernel C: brute-force exact 3-NN per query ----------------
// Shared layout (dynamic, 64KB): pairs of supports, packed for f32x2:
//   pA[p] = (x0, x1, y0, y1)    pB[p] = (z0, z1, nrm0, nrm1)
__global__ __launch_bounds__(256) void knn_kernel(const float* __restrict__ xyzq,
                                                  const float* __restrict__ xyzs) {
    extern __shared__ float4 sh[];
    float4* pA = sh;
    float4* pB = sh + (MM / 2);

    int b = blockIdx.y;
    const float* sb = xyzs + (size_t)b * MM * 3;
    for (int p = threadIdx.x; p < MM / 2; p += 256) {
        float x0 = sb[6 * p + 0], y0 = sb[6 * p + 1], z0 = sb[6 * p + 2];
        float x1 = sb[6 * p + 3], y1 = sb[6 * p + 4], z1 = sb[6 * p + 5];
        pA[p] = make_float4(x0, x1, y0, y1);
        pB[p] = make_float4(z0, z1,
                            x0 * x0 + y0 * y0 + z0 * z0,
                            x1 * x1 + y1 * y1 + z1 * z1);
    }
    __syncthreads();

    int n = blockIdx.x * 256 + threadIdx.x;
    const float* q = xyzq + ((size_t)b * NN + n) * 3;
    float qx = q[0], qy = q[1], qz = q[2];
    float qn = qx * qx + qy * qy + qz * qz;

    unsigned long long qx2 = pk2(qx, qx), qy2 = pk2(qy, qy), qz2 = pk2(qz, qz);
    unsigned long long qn2 = pk2(qn, qn), m2 = pk2(-2.0f, -2.0f);

    float d0 = INFINITY, d1 = INFINITY, d2 = INFINITY;
    int i0 = 0, i1 = 0, i2 = 0;

#define INSERT(dv, mv)                                              \
    do {                                                            \
        if ((dv) < d0)      { d2 = d1; i2 = i1; d1 = d0; i1 = i0;   \
                              d0 = (dv); i0 = (mv); }               \
        else if ((dv) < d1) { d2 = d1; i2 = i1;                     \
                              d1 = (dv); i1 = (mv); }               \
        else if ((dv) < d2) { d2 = (dv); i2 = (mv); }               \
    } while (0)

    #pragma unroll 4
    for (int p = 0; p < MM / 2; p++) {
        float4 A  = pA[p];
        float4 Bv = pB[p];
        unsigned long long X  = pk2(A.x, A.y);
        unsigned long long Y  = pk2(A.z, A.w);
        unsigned long long Z  = pk2(Bv.x, Bv.y);
        unsigned long long SN = pk2(Bv.z, Bv.w);
        unsigned long long t = mul2(X, qx2);
        t = fma2(Y, qy2, t);
        t = fma2(Z, qz2, t);
        unsigned long long s = add2(SN, qn2);       // (qq + ss), matches reference grouping
        unsigned long long dd = fma2(t, m2, s);     // (qq + ss) - 2*dot
        float lo, hi;
        upk2(lo, hi, dd);
        if (fminf(lo, hi) < d2) {
            INSERT(lo, 2 * p);
            INSERT(hi, 2 * p + 1);
        }
    }
#undef INSERT

    float r0 = 1.0f / (d0 + 1e-8f);
    float r1 = 1.0f / (d1 + 1e-8f);
    float r2 = 1.0f / (d2 + 1e-8f);
    float rs = 1.0f / (r0 + r1 + r2);
    int base = (b * NN + n) * 3;
    g_knn[base + 0] = i0;  g_knn[base + 1] = i1;  g_knn[base + 2] = i2;
    g_wgt[base + 0] = r0 * rs;  g_wgt[base + 1] = r1 * rs;  g_wgt[base + 2] = r2 * rs;
}

// ---------------- Kernel D: out[b,c,n] = sum_j pooled[b, knn_j(n), c] * w_j(n) ----------------
// 32 queries x 128 channels per block; SMEM transpose so the (B,C,N) store is coalesced.
__global__ __launch_bounds__(256) void interp_kernel(float* __restrict__ out) {
    __shared__ float tile[32][129];
    int b  = blockIdx.y;
    int n0 = blockIdx.x * 32;
    int t  = threadIdx.x;
    int c4  = t & 31;        // float4 index over channels (c = 4*c4 .. 4*c4+3)
    int nlo = t >> 5;        // 0..7

    const float* pb = g_pooled + (size_t)b * MM * CC;

    #pragma unroll
    for (int i = 0; i < 4; i++) {
        int nl = nlo + 8 * i;
        int n  = n0 + nl;
        int base = (b * NN + n) * 3;
        int j0 = g_knn[base + 0], j1 = g_knn[base + 1], j2 = g_knn[base + 2];
        float w0 = g_wgt[base + 0], w1 = g_wgt[base + 1], w2 = g_wgt[base + 2];
        const float4* p0 = (const float4*)(pb + (size_t)j0 * CC);
        const float4* p1 = (const float4*)(pb + (size_t)j1 * CC);
        const float4* p2 = (const float4*)(pb + (size_t)j2 * CC);
        float4 a = p0[c4], bb = p1[c4], cc = p2[c4];
        tile[nl][4 * c4 + 0] = w0 * a.x + w1 * bb.x + w2 * cc.x;
        tile[nl][4 * c4 + 1] = w0 * a.y + w1 * bb.y + w2 * cc.y;
        tile[nl][4 * c4 + 2] = w0 * a.z + w1 * bb.z + w2 * cc.z;
        tile[nl][4 * c4 + 3] = w0 * a.w + w1 * bb.w + w2 * cc.w;
    }
    __syncthreads();

    float* ob = out + (size_t)b * CC * NN;
    int nl = t & 31;
    #pragma unroll
    for (int i = 0; i < 16; i++) {
        int c = (t >> 5) + 8 * i;
        ob[(size_t)c * NN + n0 + nl] = tile[nl][c];
    }
}

extern "C" void kernel_launch(void* const* d_in, const int* in_sizes, int n_in,
                              void* d_out, int out_size) {
    const float* feature  = (const float*)d_in[0];
    const int*   pool_idx = (const int*)  d_in[1];
    const float* xyzq     = (const float*)d_in[2];
    const float* xyzs     = (const float*)d_in[3];
    float* out = (float*)d_out;

    cudaFuncSetAttribute(knn_kernel, cudaFuncAttributeMaxDynamicSharedMemorySize, 65536);

    transpose_kernel<<<dim3(NN / 32, CC / 32, BB), dim3(32, 8)>>>(feature);
    pool_kernel<<<dim3(MM, BB), CC>>>(pool_idx);
    knn_kernel<<<dim3(NN / 256, BB), 256, 65536>>>(xyzq, xyzs);
    interp_kernel<<<dim3(NN / 32, BB), 256>>>(out);
}

// round 2
// speedup vs baseline: 2.1156x; 2.1156x over previous
#include <cuda_runtime.h>
#include <math.h>

// Problem constants
#define BB 4
#define CC 128
#define NN 16384
#define MM 4096
#define KK 16
#define G  16
#define NC (G*G*G)   // 4096 cells

// Scratch (allocation-free rule: __device__ globals)
__device__ float  g_featT[BB * NN * CC];    // (B,N,C)
__device__ float  g_pooled[BB * MM * CC];   // (B,M,C)
__device__ int    g_knn[BB * NN * 3];
__device__ float  g_wgt[BB * NN * 3];

// Uniform-grid structures (per batch)
__device__ int    g_scnt[BB * NC];
__device__ int    g_qcnt[BB * NC];
__device__ int    g_sstart[BB * (NC + 1)];
__device__ int    g_qstart[BB * (NC + 1)];   // (unused downstream; kept for symmetry)
__device__ int    g_scur[BB * NC];
__device__ int    g_qcur[BB * NC];
__device__ float4 g_spts[BB * MM];           // x,y,z, |s|^2  (cell-sorted)
__device__ int    g_sidx[BB * MM];           // original support index
__device__ float4 g_qpts[BB * NN];           // x,y,z, bitcast(query idx) (cell-sorted)

__device__ __forceinline__ int cellof(float v) {
    int c = (int)(v * (float)G);
    return c < 0 ? 0 : (c > G - 1 ? G - 1 : c);
}

// ---------------- grid build ----------------
__global__ void k_zero() {
    int t = blockIdx.x * blockDim.x + threadIdx.x;
    if (t < BB * NC) { g_scnt[t] = 0; g_qcnt[t] = 0; }
}

__global__ void k_count(const float* __restrict__ xyzs, const float* __restrict__ xyzq) {
    int t = blockIdx.x * blockDim.x + threadIdx.x;
    if (t < BB * MM) {
        int b = t >> 12, m = t & (MM - 1);
        const float* p = xyzs + (size_t)(b * MM + m) * 3;
        int c = (cellof(p[2]) * G + cellof(p[1])) * G + cellof(p[0]);
        atomicAdd(&g_scnt[b * NC + c], 1);
    } else if (t < BB * (MM + NN)) {
        int u = t - BB * MM;
        int b = u >> 14, n = u & (NN - 1);
        const float* p = xyzq + (size_t)(b * NN + n) * 3;
        int c = (cellof(p[2]) * G + cellof(p[1])) * G + cellof(p[0]);
        atomicAdd(&g_qcnt[b * NC + c], 1);
    }
}

// One block per (batch, which). 1024 threads, 4 cells/thread.
__global__ void k_scan() {
    __shared__ int ssum[1024];
    int which = blockIdx.x & 1;          // 0 = supports, 1 = queries
    int b = blockIdx.x >> 1;
    int* cnt   = (which ? g_qcnt   : g_scnt)   + b * NC;
    int* start = (which ? g_qstart : g_sstart) + b * (NC + 1);
    int* cur   = (which ? g_qcur   : g_scur)   + b * NC;
    int t = threadIdx.x;
    int4 v = ((const int4*)cnt)[t];
    int s = v.x + v.y + v.z + v.w;
    ssum[t] = s;
    __syncthreads();
    for (int off = 1; off < 1024; off <<= 1) {
        int y = (t >= off) ? ssum[t - off] : 0;
        __syncthreads();
        ssum[t] += y;
        __syncthreads();
    }
    int e = ssum[t] - s;   // exclusive prefix
    start[4*t+0] = e; cur[4*t+0] = e; e += v.x;
    start[4*t+1] = e; cur[4*t+1] = e; e += v.y;
    start[4*t+2] = e; cur[4*t+2] = e; e += v.z;
    start[4*t+3] = e; cur[4*t+3] = e;
    if (t == 1023) start[NC] = ssum[1023];
}

__global__ void k_scatter(const float* __restrict__ xyzs, const float* __restrict__ xyzq) {
    int t = blockIdx.x * blockDim.x + threadIdx.x;
    if (t < BB * MM) {
        int b = t >> 12, m = t & (MM - 1);
        const float* p = xyzs + (size_t)(b * MM + m) * 3;
        float x = p[0], y = p[1], z = p[2];
        int c = (cellof(z) * G + cellof(y)) * G + cellof(x);
        int pos = atomicAdd(&g_scur[b * NC + c], 1);
        g_spts[b * MM + pos] = make_float4(x, y, z, x*x + y*y + z*z);
        g_sidx[b * MM + pos] = m;
    } else if (t < BB * (MM + NN)) {
        int u = t - BB * MM;
        int b = u >> 14, n = u & (NN - 1);
        const float* p = xyzq + (size_t)(b * NN + n) * 3;
        float x = p[0], y = p[1], z = p[2];
        int c = (cellof(z) * G + cellof(y)) * G + cellof(x);
        int pos = atomicAdd(&g_qcur[b * NC + c], 1);
        g_qpts[b * NN + pos] = make_float4(x, y, z, __int_as_float(n));
    }
}

// ---------------- Kernel A: transpose feature (B,C,N) -> (B,N,C) ----------------
__global__ void transpose_kernel(const float* __restrict__ feat) {
    __shared__ float tile[32][33];
    int b  = blockIdx.z;
    int n0 = blockIdx.x * 32;
    int c0 = blockIdx.y * 32;
    int tx = threadIdx.x, ty = threadIdx.y;   // 32 x 8
    const float* fb = feat + (size_t)b * CC * NN;
    #pragma unroll
    for (int i = 0; i < 32; i += 8)
        tile[ty + i][tx] = fb[(size_t)(c0 + ty + i) * NN + n0 + tx];
    __syncthreads();
    float* ft = g_featT + (size_t)b * NN * CC;
    #pragma unroll
    for (int i = 0; i < 32; i += 8)
        ft[(size_t)(n0 + ty + i) * CC + c0 + tx] = tile[tx][ty + i];
}

// ---------------- Kernel B: pooled[b,m,c] = max_k featT[b, idx[b,m,k], c] ----------------
__global__ void pool_kernel(const int* __restrict__ pool_idx) {
    int b = blockIdx.y;
    int m = blockIdx.x;
    int c = threadIdx.x;  // 128
    __shared__ int sidx[KK];
    if (threadIdx.x < KK)
        sidx[threadIdx.x] = pool_idx[((size_t)b * MM + m) * KK + threadIdx.x];
    __syncthreads();
    const float* fb = g_featT + (size_t)b * NN * CC;
    float v = -INFINITY;
    #pragma unroll
    for (int k = 0; k < KK; k++)
        v = fmaxf(v, fb[(size_t)sidx[k] * CC + c]);
    g_pooled[((size_t)b * MM + m) * CC + c] = v;
}

// ---------------- Kernel C: exact 3-NN via uniform grid, expanding shells ----------------
// SMEM: spts float4[4096] (64KB) | sstart int[4097+pad] | sidx int[4096]
#define KNN_SMEM (65536 + 4112*4 + 16384)

__global__ __launch_bounds__(256) void knn_kernel() {
    extern __shared__ char sh[];
    float4* spts  = (float4*)sh;
    int*    sstart = (int*)(sh + 65536);
    int*    sidx   = (int*)(sh + 65536 + 4112*4);

    int b = blockIdx.y;
    // cooperative smem fill
    for (int i = threadIdx.x; i < MM; i += 256) {
        spts[i] = g_spts[b * MM + i];
        sidx[i] = g_sidx[b * MM + i];
    }
    for (int i = threadIdx.x; i < NC + 1; i += 256)
        sstart[i] = g_sstart[b * (NC + 1) + i];
    __syncthreads();

    int t = blockIdx.x * 256 + threadIdx.x;
    float4 qp = g_qpts[b * NN + t];
    float qx = qp.x, qy = qp.y, qz = qp.z;
    int   n  = __float_as_int(qp.w);
    float qn = qx*qx + qy*qy + qz*qz;
    int ci = cellof(qx), cj = cellof(qy), ck = cellof(qz);

    const float h = 1.0f / (float)G;
    float d0 = 1e30f, d1 = 1e30f, d2 = 1e30f;
    int   i0 = 0,     i1 = 0,     i2 = 0;

#define INSERT(dv, mv)                                              \
    do {                                                            \
        if ((dv) < d0)      { d2 = d1; i2 = i1; d1 = d0; i1 = i0;   \
                              d0 = (dv); i0 = (mv); }               \
        else if ((dv) < d1) { d2 = d1; i2 = i1;                     \
                              d1 = (dv); i1 = (mv); }               \
        else                { d2 = (dv); i2 = (mv); }               \
    } while (0)

#define SCAN_SPAN(cs, ce)                                           \
    for (int p = (cs); p < (ce); p++) {                             \
        float4 sp = spts[p];                                        \
        float dd = (qn + sp.w)                                      \
                 - 2.0f * (qx*sp.x + qy*sp.y + qz*sp.z);            \
        if (dd < d2) { int mi = sidx[p]; INSERT(dd, mi); }          \
    }

    for (int r = 0; r < G; r++) {
        int zlo = ck - r < 0 ? 0 : ck - r;
        int zhi = ck + r > G - 1 ? G - 1 : ck + r;
        for (int z = zlo; z <= zhi; z++) {
            bool zface = (z - ck == r) || (ck - z == r);
            int ylo = cj - r < 0 ? 0 : cj - r;
            int yhi = cj + r > G - 1 ? G - 1 : cj + r;
            for (int y = ylo; y <= yhi; y++) {
                bool face = zface || (y - cj == r) || (cj - y == r);
                int rowbase = (z * G + y) * G;
                if (face) {
                    int x0 = ci - r < 0 ? 0 : ci - r;
                    int x1 = ci + r > G - 1 ? G - 1 : ci + r;
                    int cs = sstart[rowbase + x0];
                    int ce = sstart[rowbase + x1 + 1];
                    SCAN_SPAN(cs, ce);
                } else {
                    int xa = ci - r;
                    if (xa >= 0) {
                        int cc0 = rowbase + xa;
                        SCAN_SPAN(sstart[cc0], sstart[cc0 + 1]);
                    }
                    int xb = ci + r;
                    if (xb <= G - 1) {
                        int cc1 = rowbase + xb;
                        SCAN_SPAN(sstart[cc1], sstart[cc1 + 1]);
                    }
                }
            }
        }
        // termination bound: any unscanned point is at true distance >= bound
        if (d2 < 1e30f) {
            float bl = (ci - r > 0)     ? qx - (float)(ci - r) * h     : 1e30f;
            float br = (ci + r < G - 1) ? (float)(ci + r + 1) * h - qx : 1e30f;
            float bd = (cj - r > 0)     ? qy - (float)(cj - r) * h     : 1e30f;
            float bu = (cj + r < G - 1) ? (float)(cj + r + 1) * h - qy : 1e30f;
            float bn = (ck - r > 0)     ? qz - (float)(ck - r) * h     : 1e30f;
            float bf = (ck + r < G - 1) ? (float)(ck + r + 1) * h - qz : 1e30f;
            float bound = fminf(fminf(fminf(bl, br), fminf(bd, bu)), fminf(bn, bf));
            if (bound * bound >= d2 + 1e-5f) break;
        }
    }
#undef SCAN_SPAN
#undef INSERT

    float r0 = 1.0f / (d0 + 1e-8f);
    float r1 = 1.0f / (d1 + 1e-8f);
    float r2 = 1.0f / (d2 + 1e-8f);
    float rs = 1.0f / (r0 + r1 + r2);
    int base = (b * NN + n) * 3;
    g_knn[base + 0] = i0;  g_knn[base + 1] = i1;  g_knn[base + 2] = i2;
    g_wgt[base + 0] = r0 * rs;  g_wgt[base + 1] = r1 * rs;  g_wgt[base + 2] = r2 * rs;
}

// ---------------- Kernel D: out[b,c,n] = sum_j pooled[b, knn_j(n), c] * w_j(n) ----------------
__global__ __launch_bounds__(256) void interp_kernel(float* __restrict__ out) {
    __shared__ float tile[32][129];
    int b  = blockIdx.y;
    int n0 = blockIdx.x * 32;
    int t  = threadIdx.x;
    int c4  = t & 31;
    int nlo = t >> 5;

    const float* pb = g_pooled + (size_t)b * MM * CC;

    #pragma unroll
    for (int i = 0; i < 4; i++) {
        int nl = nlo + 8 * i;
        int n  = n0 + nl;
        int base = (b * NN + n) * 3;
        int j0 = g_knn[base + 0], j1 = g_knn[base + 1], j2 = g_knn[base + 2];
        float w0 = g_wgt[base + 0], w1 = g_wgt[base + 1], w2 = g_wgt[base + 2];
        const float4* p0 = (const float4*)(pb + (size_t)j0 * CC);
        const float4* p1 = (const float4*)(pb + (size_t)j1 * CC);
        const float4* p2 = (const float4*)(pb + (size_t)j2 * CC);
        float4 a = p0[c4], bb = p1[c4], cc = p2[c4];
        tile[nl][4 * c4 + 0] = w0 * a.x + w1 * bb.x + w2 * cc.x;
        tile[nl][4 * c4 + 1] = w0 * a.y + w1 * bb.y + w2 * cc.y;
        tile[nl][4 * c4 + 2] = w0 * a.z + w1 * bb.z + w2 * cc.z;
        tile[nl][4 * c4 + 3] = w0 * a.w + w1 * bb.w + w2 * cc.w;
    }
    __syncthreads();

    float* ob = out + (size_t)b * CC * NN;
    int nl = t & 31;
    #pragma unroll
    for (int i = 0; i < 16; i++) {
        int c = (t >> 5) + 8 * i;
        ob[(size_t)c * NN + n0 + nl] = tile[nl][c];
    }
}

extern "C" void kernel_launch(void* const* d_in, const int* in_sizes, int n_in,
                              void* d_out, int out_size) {
    const float* feature  = (const float*)d_in[0];
    const int*   pool_idx = (const int*)  d_in[1];
    const float* xyzq     = (const float*)d_in[2];
    const float* xyzs     = (const float*)d_in[3];
    float* out = (float*)d_out;

    cudaFuncSetAttribute(knn_kernel, cudaFuncAttributeMaxDynamicSharedMemorySize, KNN_SMEM);

    // grid build for exact 3-NN
    k_zero<<<(BB * NC + 255) / 256, 256>>>();
    k_count<<<(BB * (MM + NN) + 255) / 256, 256>>>(xyzs, xyzq);
    k_scan<<<2 * BB, 1024>>>();
    k_scatter<<<(BB * (MM + NN) + 255) / 256, 256>>>(xyzs, xyzq);

    // feature path
    transpose_kernel<<<dim3(NN / 32, CC / 32, BB), dim3(32, 8)>>>(feature);
    pool_kernel<<<dim3(MM, BB), CC>>>(pool_idx);

    // knn + interpolation
    knn_kernel<<<dim3(NN / 256, BB), 256, KNN_SMEM>>>();
    interp_kernel<<<dim3(NN / 32, BB), 256>>>(out);
}